// round 7
// baseline (speedup 1.0000x reference)
#include <cuda_runtime.h>

#define N_NODES 100000
#define N_EDGES 1600000
#define D 64
#define SCAN_BLK 1024
#define N_PARTIAL ((N_NODES + SCAN_BLK - 1) / SCAN_BLK)   // 98

typedef unsigned long long u64;

// Scratch (allocation-free rule: device globals)
__device__ int g_count[N_NODES];
__device__ int g_off[N_NODES + 1];
__device__ int g_cursor[N_NODES];
__device__ int g_partial[128];
__device__ u64 g_csr[N_EDGES];          // packed (w_bits << 32) | src

// ---- packed fp32x2 helpers (sm_103a FFMA2) --------------------------------
__device__ __forceinline__ void ffma2(u64& d, u64 a, u64 b) {
    asm("fma.rn.f32x2 %0, %1, %2, %0;" : "+l"(d) : "l"(a), "l"(b));
}
__device__ __forceinline__ u64 dup2(float x) {
    u64 r; asm("mov.b64 %0, {%1, %1};" : "=l"(r) : "f"(x)); return r;
}
__device__ __forceinline__ void unpack2(float& lo, float& hi, u64 v) {
    asm("mov.b64 {%0, %1}, %2;" : "=f"(lo), "=f"(hi) : "l"(v));
}

// ---------------------------------------------------------------------------
// k0: zero degree counts
// ---------------------------------------------------------------------------
__global__ void zero_count_kernel() {
    int i = blockIdx.x * blockDim.x + threadIdx.x;
    if (i < N_NODES) g_count[i] = 0;
}

// ---------------------------------------------------------------------------
// k1: histogram of dst
// ---------------------------------------------------------------------------
__global__ void __launch_bounds__(256) hist_kernel(const int* __restrict__ dst) {
    int e = blockIdx.x * blockDim.x + threadIdx.x;
    if (e < N_EDGES) atomicAdd(&g_count[dst[e]], 1);
}

// ---------------------------------------------------------------------------
// k2a: per-1024-segment sums -> g_partial
// ---------------------------------------------------------------------------
__global__ void __launch_bounds__(256) partial_kernel() {
    __shared__ int wsum[8];
    int t = threadIdx.x;
    int base = blockIdx.x * SCAN_BLK + t * 4;
    int s = 0;
#pragma unroll
    for (int k = 0; k < 4; k++) {
        int idx = base + k;
        if (idx < N_NODES) s += g_count[idx];
    }
#pragma unroll
    for (int d = 16; d > 0; d >>= 1) s += __shfl_down_sync(0xFFFFFFFFu, s, d);
    if ((t & 31) == 0) wsum[t >> 5] = s;
    __syncthreads();
    if (t == 0) {
        int tot = 0;
#pragma unroll
        for (int w = 0; w < 8; w++) tot += wsum[w];
        g_partial[blockIdx.x] = tot;
    }
}

// ---------------------------------------------------------------------------
// k2b: parallel exclusive scan of 98 partials
// ---------------------------------------------------------------------------
__global__ void __launch_bounds__(128) scan_partial_kernel() {
    __shared__ int wtot[4];
    __shared__ int wbase[4];
    int t = threadIdx.x;
    int lane = t & 31, wid = t >> 5;
    int v = (t < N_PARTIAL) ? g_partial[t] : 0;
    int s = v;
#pragma unroll
    for (int d = 1; d < 32; d <<= 1) {
        int u = __shfl_up_sync(0xFFFFFFFFu, s, d);
        if (lane >= d) s += u;
    }
    if (lane == 31) wtot[wid] = s;
    __syncthreads();
    if (t == 0) {
        int run = 0;
#pragma unroll
        for (int w = 0; w < 4; w++) { wbase[w] = run; run += wtot[w]; }
    }
    __syncthreads();
    int excl = (s - v) + wbase[wid];
    if (t < N_PARTIAL) g_partial[t] = excl;
    if (t == N_PARTIAL - 1) g_off[N_NODES] = excl + v;
}

// ---------------------------------------------------------------------------
// k2c: per-segment exclusive scan + base -> g_off, g_cursor
// ---------------------------------------------------------------------------
__global__ void __launch_bounds__(256) offsets_kernel() {
    __shared__ int wsum[8];
    __shared__ int wbase[8];
    int t = threadIdx.x;
    int lane = t & 31, wid = t >> 5;
    int base = blockIdx.x * SCAN_BLK + t * 4;

    int c[4];
    int s = 0;
#pragma unroll
    for (int k = 0; k < 4; k++) {
        int idx = base + k;
        c[k] = (idx < N_NODES) ? g_count[idx] : 0;
        s += c[k];
    }
    int own = s;
#pragma unroll
    for (int d = 1; d < 32; d <<= 1) {
        int v = __shfl_up_sync(0xFFFFFFFFu, s, d);
        if (lane >= d) s += v;
    }
    if (lane == 31) wsum[wid] = s;
    __syncthreads();
    if (t == 0) {
        int run = 0;
#pragma unroll
        for (int w = 0; w < 8; w++) { wbase[w] = run; run += wsum[w]; }
    }
    __syncthreads();

    int excl = (s - own) + wbase[wid] + g_partial[blockIdx.x];
#pragma unroll
    for (int k = 0; k < 4; k++) {
        int idx = base + k;
        if (idx < N_NODES) {
            g_off[idx] = excl;
            g_cursor[idx] = excl;
        }
        excl += c[k];
    }
}

// ---------------------------------------------------------------------------
// k3: fill CSR bins — one packed 8B store per edge
// ---------------------------------------------------------------------------
__global__ void __launch_bounds__(256) fill_kernel(const int* __restrict__ src,
                                                   const int* __restrict__ dst,
                                                   const float* __restrict__ w) {
    int e = blockIdx.x * blockDim.x + threadIdx.x;
    if (e >= N_EDGES) return;
    int d = dst[e];
    int p = atomicAdd(&g_cursor[d], 1);
    u64 packed = ((u64)__float_as_uint(w[e]) << 32) | (unsigned)src[e];
    g_csr[p] = packed;
}

// ---------------------------------------------------------------------------
// k4 (FUSED): gather-to-smem + FFMA2 GEMM
// Block: 256 threads, tile 128 nodes x 64 cols.
// Phase A: load weights + feat tile (transposed) into smem.
// Phase B: warp-per-node CSR gather -> neighS[k][n] (transposed).
// Phase C: GEMM, thread (jg=t&15, ng=t>>4): cols {jg+16j}, nodes ng*8..+7
//          as 4 adjacent-node f32x2 pairs.
// ---------------------------------------------------------------------------
#define BN 130
__global__ void __launch_bounds__(256) fused_kernel(
        const float2* __restrict__ feat2,
        const float* __restrict__ W_neigh,
        const float* __restrict__ W_self,
        const float* __restrict__ bias,
        float* __restrict__ out) {
    __shared__ float featS[D][BN];
    __shared__ float neighS[D][BN];
    __shared__ float WsT[D][65];
    __shared__ float WnT[D][65];
    __shared__ float biasS[D];

    const int t = threadIdx.x;
    const long long node0 = (long long)blockIdx.x * 128;
    const float* feat = (const float*)feat2;

    if (t < D) biasS[t] = bias[t];

    // Weights transposed into [k][j]
    for (int idx = t; idx < D * D; idx += 256) {
        int j = idx >> 6, k = idx & 63;
        WsT[k][j] = W_self[idx];
        WnT[k][j] = W_neigh[idx];
    }
    // feat tile transposed into [k][n]; zero tail.
    for (int idx = t; idx < 128 * D; idx += 256) {
        int n = idx >> 7, k = idx & 127;   // careful: idx = n*? -- use explicit
        // recompute properly: n in [0,128), k in [0,64)
        n = idx >> 6; k = idx & 63;
        long long node = node0 + n;
        featS[k][n] = (node < N_NODES) ? feat[node * D + k] : 0.f;
    }

    // Phase B: gather. Warp per node, lane owns cols {2*lane, 2*lane+1}.
    {
        int wid = t >> 5, lane = t & 31;
        for (int n = wid; n < 128; n += 8) {
            long long node = node0 + n;
            float2 a0 = make_float2(0.f, 0.f);
            float2 a1 = make_float2(0.f, 0.f);
            float rdeg = 0.f;
            if (node < N_NODES) {
                int beg = g_off[node];
                int end = g_off[node + 1];
                int i = beg;
                for (; i + 1 < end; i += 2) {
                    u64 p0 = g_csr[i];
                    u64 p1 = g_csr[i + 1];
                    int   s0 = (int)(unsigned)p0;
                    int   s1 = (int)(unsigned)p1;
                    float w0 = __uint_as_float((unsigned)(p0 >> 32));
                    float w1 = __uint_as_float((unsigned)(p1 >> 32));
                    float2 v0 = feat2[(long long)s0 * (D / 2) + lane];
                    float2 v1 = feat2[(long long)s1 * (D / 2) + lane];
                    a0.x += v0.x * w0; a0.y += v0.y * w0;
                    a1.x += v1.x * w1; a1.y += v1.y * w1;
                }
                if (i < end) {
                    u64 p0 = g_csr[i];
                    int   s0 = (int)(unsigned)p0;
                    float w0 = __uint_as_float((unsigned)(p0 >> 32));
                    float2 v0 = feat2[(long long)s0 * (D / 2) + lane];
                    a0.x += v0.x * w0; a0.y += v0.y * w0;
                }
                rdeg = 1.0f / fmaxf((float)(end - beg), 1.0f);
            }
            neighS[2 * lane][n]     = (a0.x + a1.x) * rdeg;
            neighS[2 * lane + 1][n] = (a0.y + a1.y) * rdeg;
        }
    }
    __syncthreads();

    // Phase C: GEMM
    const int jg = t & 15;   // cols jg + 16*j, j=0..3
    const int ng = t >> 4;   // nodes ng*8 .. ng*8+7

    u64 acc[4][4];
#pragma unroll
    for (int j = 0; j < 4; j++) {
        u64 b = dup2(biasS[jg + 16 * j]);
#pragma unroll
        for (int np = 0; np < 4; np++) acc[np][j] = b;
    }

#pragma unroll 4
    for (int k = 0; k < D; k++) {
        u64 a2[4], c2[4];
#pragma unroll
        for (int np = 0; np < 4; np++) {
            a2[np] = *reinterpret_cast<const u64*>(&featS[k][ng * 8 + 2 * np]);
            c2[np] = *reinterpret_cast<const u64*>(&neighS[k][ng * 8 + 2 * np]);
        }
        u64 bs2[4], bn2[4];
#pragma unroll
        for (int j = 0; j < 4; j++) {
            bs2[j] = dup2(WsT[k][jg + 16 * j]);
            bn2[j] = dup2(WnT[k][jg + 16 * j]);
        }
#pragma unroll
        for (int np = 0; np < 4; np++)
#pragma unroll
            for (int j = 0; j < 4; j++) {
                ffma2(acc[np][j], a2[np], bs2[j]);
                ffma2(acc[np][j], c2[np], bn2[j]);
            }
    }

    // Stores
#pragma unroll
    for (int np = 0; np < 4; np++) {
        long long nA = node0 + ng * 8 + 2 * np;
        long long nB = nA + 1;
        bool okA = nA < N_NODES, okB = nB < N_NODES;
#pragma unroll
        for (int j = 0; j < 4; j++) {
            float lo, hi;
            unpack2(lo, hi, acc[np][j]);
            int col = jg + 16 * j;
            if (okA) out[nA * D + col] = lo;
            if (okB) out[nB * D + col] = hi;
        }
    }
}

// ---------------------------------------------------------------------------
// Launch
// ---------------------------------------------------------------------------
extern "C" void kernel_launch(void* const* d_in, const int* in_sizes, int n_in,
                              void* d_out, int out_size) {
    const float* feat = (const float*)d_in[0];
    const int*   src  = (const int*)d_in[1];
    const int*   dst  = (const int*)d_in[2];
    const float* ew   = (const float*)d_in[3];
    const float* Wn   = (const float*)d_in[4];
    const float* Wsf  = (const float*)d_in[5];
    const float* bias = (const float*)d_in[6];
    float* out = (float*)d_out;

    (void)in_sizes; (void)n_in; (void)out_size;

    const int EB = (N_EDGES + 255) / 256;     // 6250

    zero_count_kernel<<<(N_NODES + 255) / 256, 256>>>();
    hist_kernel<<<EB, 256>>>(dst);
    partial_kernel<<<N_PARTIAL, 256>>>();
    scan_partial_kernel<<<1, 128>>>();
    offsets_kernel<<<N_PARTIAL, 256>>>();
    fill_kernel<<<EB, 256>>>(src, dst, ew);
    fused_kernel<<<(N_NODES + 127) / 128, 256>>>((const float2*)feat, Wn, Wsf, bias, out);
}

// round 10
// speedup vs baseline: 1.2233x; 1.2233x over previous
#include <cuda_runtime.h>

#define N_NODES 100000
#define N_EDGES 1600000
#define D 64
#define SCAN_BLK 1024
#define N_PARTIAL ((N_NODES + SCAN_BLK - 1) / SCAN_BLK)   // 98

typedef unsigned long long u64;

// Scratch (allocation-free rule: device globals)
__device__ float g_neigh[N_NODES * D];
__device__ int   g_count[N_NODES];
__device__ int   g_off[N_NODES + 1];
__device__ int   g_cursor[N_NODES];
__device__ int   g_partial[128];
__device__ u64   g_csr[N_EDGES];        // packed (w_bits << 32) | src

// ---- packed fp32x2 helpers (sm_103a FFMA2) --------------------------------
__device__ __forceinline__ void ffma2(u64& d, u64 a, u64 b) {
    asm("fma.rn.f32x2 %0, %1, %2, %0;" : "+l"(d) : "l"(a), "l"(b));
}
__device__ __forceinline__ u64 dup2(float x) {
    u64 r; asm("mov.b64 %0, {%1, %1};" : "=l"(r) : "f"(x)); return r;
}
__device__ __forceinline__ void unpack2(float& lo, float& hi, u64 v) {
    asm("mov.b64 {%0, %1}, %2;" : "=f"(lo), "=f"(hi) : "l"(v));
}

// ---------------------------------------------------------------------------
// k0: zero degree counts (+ constant tail offset)
// ---------------------------------------------------------------------------
__global__ void zero_count_kernel() {
    int i = blockIdx.x * blockDim.x + threadIdx.x;
    if (i < N_NODES) g_count[i] = 0;
    if (i == 0) g_off[N_NODES] = N_EDGES;
}

// ---------------------------------------------------------------------------
// k1: histogram of dst
// ---------------------------------------------------------------------------
__global__ void __launch_bounds__(256) hist_kernel(const int* __restrict__ dst) {
    int e = blockIdx.x * blockDim.x + threadIdx.x;
    if (e < N_EDGES) atomicAdd(&g_count[dst[e]], 1);
}

// ---------------------------------------------------------------------------
// k2: per-1024-segment sums -> g_partial
// ---------------------------------------------------------------------------
__global__ void __launch_bounds__(256) partial_kernel() {
    __shared__ int wsum[8];
    int t = threadIdx.x;
    int base = blockIdx.x * SCAN_BLK + t * 4;
    int s = 0;
#pragma unroll
    for (int k = 0; k < 4; k++) {
        int idx = base + k;
        if (idx < N_NODES) s += g_count[idx];
    }
#pragma unroll
    for (int d = 16; d > 0; d >>= 1) s += __shfl_down_sync(0xFFFFFFFFu, s, d);
    if ((t & 31) == 0) wsum[t >> 5] = s;
    __syncthreads();
    if (t == 0) {
        int tot = 0;
#pragma unroll
        for (int w = 0; w < 8; w++) tot += wsum[w];
        g_partial[blockIdx.x] = tot;
    }
}

// ---------------------------------------------------------------------------
// k3: per-segment exclusive scan; block base computed by inline masked
//     reduction over g_partial[0..bid) (no separate scan kernel).
// ---------------------------------------------------------------------------
__global__ void __launch_bounds__(256) offsets_kernel() {
    __shared__ int wsum[8];
    __shared__ int wbase[8];
    __shared__ int sbase;
    int t = threadIdx.x;
    int lane = t & 31, wid = t >> 5;
    int bid = blockIdx.x;

    // --- base = sum of partials before this block ---
    int p = (t < bid) ? g_partial[t] : 0;    // bid <= 97 < 256
#pragma unroll
    for (int d = 16; d > 0; d >>= 1) p += __shfl_down_sync(0xFFFFFFFFu, p, d);
    if (lane == 0) wsum[wid] = p;
    __syncthreads();
    if (t == 0) {
        int run = 0;
#pragma unroll
        for (int w = 0; w < 8; w++) run += wsum[w];
        sbase = run;
    }
    __syncthreads();

    // --- per-segment scan (1024 counts, 4 per thread) ---
    int base = bid * SCAN_BLK + t * 4;
    int c[4];
    int s = 0;
#pragma unroll
    for (int k = 0; k < 4; k++) {
        int idx = base + k;
        c[k] = (idx < N_NODES) ? g_count[idx] : 0;
        s += c[k];
    }
    int own = s;
#pragma unroll
    for (int d = 1; d < 32; d <<= 1) {
        int v = __shfl_up_sync(0xFFFFFFFFu, s, d);
        if (lane >= d) s += v;
    }
    if (lane == 31) wsum[wid] = s;
    __syncthreads();
    if (t == 0) {
        int run = 0;
#pragma unroll
        for (int w = 0; w < 8; w++) { wbase[w] = run; run += wsum[w]; }
    }
    __syncthreads();

    int excl = (s - own) + wbase[wid] + sbase;
#pragma unroll
    for (int k = 0; k < 4; k++) {
        int idx = base + k;
        if (idx < N_NODES) {
            g_off[idx] = excl;
            g_cursor[idx] = excl;
        }
        excl += c[k];
    }
}

// ---------------------------------------------------------------------------
// k4: fill CSR bins — one packed 8B store per edge
// ---------------------------------------------------------------------------
__global__ void __launch_bounds__(256) fill_kernel(const int* __restrict__ src,
                                                   const int* __restrict__ dst,
                                                   const float* __restrict__ w) {
    int e = blockIdx.x * blockDim.x + threadIdx.x;
    if (e >= N_EDGES) return;
    int d = dst[e];
    int p = atomicAdd(&g_cursor[d], 1);
    g_csr[p] = ((u64)__float_as_uint(w[e]) << 32) | (unsigned)src[e];
}

// ---------------------------------------------------------------------------
// k5: gather + mean.  One warp per node; lane owns 2 columns (float2).
// 4-edge unroll, 4 accumulators (MLP=4).
// ---------------------------------------------------------------------------
__global__ void __launch_bounds__(256) gather_kernel(const float2* __restrict__ feat2) {
    int node = blockIdx.x * 8 + (threadIdx.x >> 5);
    if (node >= N_NODES) return;
    int lane = threadIdx.x & 31;

    int beg = g_off[node];
    int end = g_off[node + 1];

    float2 a0 = make_float2(0.f, 0.f);
    float2 a1 = make_float2(0.f, 0.f);
    float2 a2 = make_float2(0.f, 0.f);
    float2 a3 = make_float2(0.f, 0.f);

    int i = beg;
    for (; i + 3 < end; i += 4) {
        u64 p0 = g_csr[i],     p1 = g_csr[i + 1];
        u64 p2 = g_csr[i + 2], p3 = g_csr[i + 3];
        float2 v0 = feat2[(long long)(unsigned)p0 * (D / 2) + lane];
        float2 v1 = feat2[(long long)(unsigned)p1 * (D / 2) + lane];
        float2 v2 = feat2[(long long)(unsigned)p2 * (D / 2) + lane];
        float2 v3 = feat2[(long long)(unsigned)p3 * (D / 2) + lane];
        float w0 = __uint_as_float((unsigned)(p0 >> 32));
        float w1 = __uint_as_float((unsigned)(p1 >> 32));
        float w2 = __uint_as_float((unsigned)(p2 >> 32));
        float w3 = __uint_as_float((unsigned)(p3 >> 32));
        a0.x += v0.x * w0; a0.y += v0.y * w0;
        a1.x += v1.x * w1; a1.y += v1.y * w1;
        a2.x += v2.x * w2; a2.y += v2.y * w2;
        a3.x += v3.x * w3; a3.y += v3.y * w3;
    }
    for (; i < end; i++) {
        u64 p0 = g_csr[i];
        float2 v0 = feat2[(long long)(unsigned)p0 * (D / 2) + lane];
        float w0 = __uint_as_float((unsigned)(p0 >> 32));
        a0.x += v0.x * w0; a0.y += v0.y * w0;
    }

    float rdeg = 1.0f / fmaxf((float)(end - beg), 1.0f);
    float2 r = make_float2(((a0.x + a1.x) + (a2.x + a3.x)) * rdeg,
                           ((a0.y + a1.y) + (a2.y + a3.y)) * rdeg);
    ((float2*)g_neigh)[(long long)node * (D / 2) + lane] = r;
}

// ---------------------------------------------------------------------------
// k6: out = feat @ Wself^T + neigh @ Wneigh^T + bias     (FFMA2 path)
// Block: 128 threads, tile 128 nodes x 64 cols; 8 node x 8 col / thread
// as 4 adjacent-node f32x2 pairs.  (R6-proven configuration.)
// ---------------------------------------------------------------------------
#define BN 130
__global__ void __launch_bounds__(128) out_kernel(
        const float* __restrict__ feat,
        const float* __restrict__ W_neigh,
        const float* __restrict__ W_self,
        const float* __restrict__ bias,
        float* __restrict__ out) {
    __shared__ float featS[D][BN];
    __shared__ float neighS[D][BN];
    __shared__ float WsT[D][65];
    __shared__ float WnT[D][65];
    __shared__ float biasS[D];

    const int t = threadIdx.x;
    const long long node0 = (long long)blockIdx.x * 128;

    if (t < D) biasS[t] = bias[t];

    for (int idx = t; idx < D * D; idx += 128) {
        int j = idx >> 6, k = idx & 63;
        WsT[k][j] = W_self[idx];
        WnT[k][j] = W_neigh[idx];
    }
    for (int idx = t; idx < 128 * D; idx += 128) {
        int n = idx >> 6, k = idx & 63;
        long long node = node0 + n;
        float fv = 0.f, nv = 0.f;
        if (node < N_NODES) {
            fv = feat[node * D + k];
            nv = g_neigh[node * D + k];
        }
        featS[k][n]  = fv;
        neighS[k][n] = nv;
    }
    __syncthreads();

    const int jg = t & 7;    // cols jg + 8*j
    const int ng = t >> 3;   // nodes ng*8 .. ng*8+7

    u64 acc[4][8];
#pragma unroll
    for (int j = 0; j < 8; j++) {
        u64 b = dup2(biasS[jg + 8 * j]);
#pragma unroll
        for (int np = 0; np < 4; np++) acc[np][j] = b;
    }

#pragma unroll 2
    for (int k = 0; k < D; k++) {
        u64 a2[4], c2[4];
#pragma unroll
        for (int np = 0; np < 4; np++) {
            a2[np] = *reinterpret_cast<const u64*>(&featS[k][ng * 8 + 2 * np]);
            c2[np] = *reinterpret_cast<const u64*>(&neighS[k][ng * 8 + 2 * np]);
        }
        u64 bs2[8], bn2[8];
#pragma unroll
        for (int j = 0; j < 8; j++) {
            bs2[j] = dup2(WsT[k][jg + 8 * j]);
            bn2[j] = dup2(WnT[k][jg + 8 * j]);
        }
#pragma unroll
        for (int np = 0; np < 4; np++)
#pragma unroll
            for (int j = 0; j < 8; j++) {
                ffma2(acc[np][j], a2[np], bs2[j]);
                ffma2(acc[np][j], c2[np], bn2[j]);
            }
    }

#pragma unroll
    for (int np = 0; np < 4; np++) {
        long long nA = node0 + ng * 8 + 2 * np;
        long long nB = nA + 1;
        bool okA = nA < N_NODES, okB = nB < N_NODES;
#pragma unroll
        for (int j = 0; j < 8; j++) {
            float lo, hi;
            unpack2(lo, hi, acc[np][j]);
            int col = jg + 8 * j;
            if (okA) out[nA * D + col] = lo;
            if (okB) out[nB * D + col] = hi;
        }
    }
}

// ---------------------------------------------------------------------------
// Launch
// ---------------------------------------------------------------------------
extern "C" void kernel_launch(void* const* d_in, const int* in_sizes, int n_in,
                              void* d_out, int out_size) {
    const float* feat = (const float*)d_in[0];
    const int*   src  = (const int*)d_in[1];
    const int*   dst  = (const int*)d_in[2];
    const float* ew   = (const float*)d_in[3];
    const float* Wn   = (const float*)d_in[4];
    const float* Wsf  = (const float*)d_in[5];
    const float* bias = (const float*)d_in[6];
    float* out = (float*)d_out;

    (void)in_sizes; (void)n_in; (void)out_size;

    const int EB = (N_EDGES + 255) / 256;     // 6250

    zero_count_kernel<<<(N_NODES + 255) / 256, 256>>>();
    hist_kernel<<<EB, 256>>>(dst);
    partial_kernel<<<N_PARTIAL, 256>>>();
    offsets_kernel<<<N_PARTIAL, 256>>>();
    fill_kernel<<<EB, 256>>>(src, dst, ew);
    gather_kernel<<<(N_NODES + 7) / 8, 256>>>((const float2*)feat);
    out_kernel<<<(N_NODES + 127) / 128, 128>>>(feat, Wn, Wsf, bias, out);
}